// round 7
// baseline (speedup 1.0000x reference)
#include <cuda_runtime.h>

#define BB 256
#define TT 512
#define DD 50
#define HH 128
#define G4 512
#define HID 256

typedef unsigned long long ull;

// ---- device scratch ----
__device__ float g_xgT[2][TT][G4][BB];   // input-gate preactivations [d][t][row][b]

__device__ __forceinline__ float sigf(float x)   { return 1.0f / (1.0f + __expf(-x)); }
__device__ __forceinline__ float tanhf_(float x) { return 2.0f / (1.0f + __expf(-2.0f * x)) - 1.0f; }

__device__ __forceinline__ ull pack2(float a, float b) {
    ull r; asm("mov.b64 %0,{%1,%2};" : "=l"(r) : "f"(a), "f"(b)); return r;
}
__device__ __forceinline__ void unpack2(ull v, float& a, float& b) {
    asm("mov.b64 {%0,%1},%2;" : "=f"(a), "=f"(b) : "l"(v));
}
__device__ __forceinline__ void fma2(ull a, ull b, ull& c) {
    asm("fma.rn.f32x2 %0,%1,%2,%0;" : "+l"(c) : "l"(a), "l"(b));
}
__device__ __forceinline__ unsigned smem_u32(const void* p) {
    unsigned r;
    asm("{ .reg .u64 t; cvta.to.shared.u64 t, %1; cvt.u32.u64 %0, t; }" : "=r"(r) : "l"(p));
    return r;
}

// ---------------------------------------------------------------------------
// Embedding lookup + input-gate GEMM -> transposed xg (unchanged)
// ---------------------------------------------------------------------------
__global__ void __launch_bounds__(256) embed_gemm(
    const int*   __restrict__ idx,
    const float* __restrict__ emb,
    const float* __restrict__ Wih_f, const float* __restrict__ bih_f, const float* __restrict__ bhh_f,
    const float* __restrict__ Wih_b, const float* __restrict__ bih_b, const float* __restrict__ bhh_b)
{
    __shared__ __align__(16) float xsA[16 * DD * 2];
    const int tid = threadIdx.x;
    const int b0  = blockIdx.x * 32;
    const int t   = blockIdx.y;

    for (int i = tid; i < 32 * DD; i += 256) {
        int b = i / DD, k = i - b * DD;
        int id = idx[(b0 + b) * TT + t];
        xsA[(b >> 1) * (2 * DD) + k * 2 + (b & 1)] = emb[id * DD + k];
    }
    __syncthreads();

    #pragma unroll 1
    for (int g = 0; g < 4; ++g) {
        int col = tid + g * 256;
        int dir = col >> 9;
        int n   = col & 511;
        const float* W = dir ? Wih_b : Wih_f;
        float bias = dir ? (bih_b[n] + bhh_b[n]) : (bih_f[n] + bhh_f[n]);

        float w[DD];
        #pragma unroll
        for (int k = 0; k < DD; ++k) w[k] = W[n * DD + k];

        ull acc[16];
        ull bp = pack2(bias, bias);
        #pragma unroll
        for (int p = 0; p < 16; ++p) acc[p] = bp;

        #pragma unroll 2
        for (int k = 0; k < DD; ++k) {
            ull w2 = pack2(w[k], w[k]);
            #pragma unroll
            for (int p = 0; p < 16; ++p) {
                ull x = *(const ull*)&xsA[p * (2 * DD) + k * 2];
                fma2(x, w2, acc[p]);
            }
        }

        float* dst = &g_xgT[dir][t][n][b0];
        #pragma unroll
        for (int p = 0; p < 16; ++p) {
            float a, b; unpack2(acc[p], a, b);
            *(float2*)&dst[2 * p] = make_float2(a, b);
        }
    }
}

// ---------------------------------------------------------------------------
// Persistent LSTM recurrence, weights IN REGISTERS.
// grid (2 k-halves, 32 b-tiles of 8, 2 dirs) = 128 CTAs, cluster (2,1,1).
// 256 threads: MAC role (g = tid>>6, kk = tid&63) -> one gate row (128 w regs),
// 8 batches via broadcast LDS of h. Update role (uk = tid>>2, bp = tid&3).
// Per-step smem traffic: h broadcast reads + 10KB gate exchange only.
// ---------------------------------------------------------------------------
__global__ void __launch_bounds__(256, 1) __cluster_dims__(2, 1, 1)
lstm_reg(const float* __restrict__ Whh_f, const float* __restrict__ Whh_b,
         const float* __restrict__ masks, float* __restrict__ out)
{
    __shared__ __align__(16) float hbuf[2][128 * 8];     // h double buffer [k][b]
    __shared__ __align__(16) float gbuf[4 * 640];        // gates [g][kk*10 + b] padded

    const int tid  = threadIdx.x;
    const int rank = blockIdx.x;               // k-half == cluster rank
    const int bt   = blockIdx.y;               // 0..31
    const int d    = blockIdx.z;
    const int K0   = rank * 64;
    const int bb0  = bt * 8;

    // MAC role
    const int g  = tid >> 6;                   // gate 0..3
    const int kk = tid & 63;                   // k-output 0..63
    const int row = g * 128 + K0 + kk;         // global gate row

    // Update role
    const int uk = tid >> 2;                   // 0..63
    const int bp = tid & 3;                    // batch pair
    const int b0 = bb0 + 2 * bp;

    const float* Whh = d ? Whh_b : Whh_f;

    // ---- load this thread's weight row into registers (kept for all steps) ----
    float w[128];
    {
        const float4* src = (const float4*)&Whh[row * 128];
        #pragma unroll
        for (int q = 0; q < 32; ++q) {
            float4 v = src[q];
            w[4 * q + 0] = v.x; w[4 * q + 1] = v.y;
            w[4 * q + 2] = v.z; w[4 * q + 3] = v.w;
        }
    }
    // zero h buffer for step 0
    for (int i = tid; i < 1024; i += 256) hbuf[0][i] = 0.f;

    // peer push addresses (both parities) for update role: h[K0+uk][2bp..]
    const unsigned off = (unsigned)(((K0 + uk) * 8 + 2 * bp) * 4);
    unsigned rem0, rem1;
    {
        unsigned a0 = smem_u32(&hbuf[0][0]) + off;
        unsigned a1 = smem_u32(&hbuf[1][0]) + off;
        unsigned pr = rank ^ 1;
        asm("mapa.shared::cluster.u32 %0, %1, %2;" : "=r"(rem0) : "r"(a0), "r"(pr));
        asm("mapa.shared::cluster.u32 %0, %1, %2;" : "=r"(rem1) : "r"(a1), "r"(pr));
    }
    float* loc0 = (float*)((char*)&hbuf[0][0] + off);
    float* loc1 = (float*)((char*)&hbuf[1][0] + off);

    // per-thread state (update role)
    float c0 = 0.f, c1 = 0.f;
    float m0 = -3.0e38f, m1 = -3.0e38f;

    const int tstep = d ? -1 : 1;
    int t = d ? (TT - 1) : 0;

    // prefetch xg pairs for step 0 (MAC role) + mask penalties (update role)
    ulonglong2 nxA, nxB;
    {
        const float* p = &g_xgT[d][t][row][bb0];
        nxA = *(const ulonglong2*)(p + 0);
        nxB = *(const ulonglong2*)(p + 4);
    }
    float pen0 = (1.0f - __ldg(&masks[(b0)     * TT + t])) * 1e8f;
    float pen1 = (1.0f - __ldg(&masks[(b0 + 1) * TT + t])) * 1e8f;

    __syncthreads();   // weights irrelevant (regs); hbuf[0] zeroed

    int cur = 0;
    for (int s = 0; s < TT; ++s) {
        // accumulators <- prefetched xg
        ull a01 = nxA.x, a23 = nxA.y, a45 = nxB.x, a67 = nxB.y;
        float npen0 = pen0, npen1 = pen1;

        // prefetch next step (latency hides under the MAC loop)
        {
            int t2 = t + tstep;
            t2 = (t2 < 0) ? 0 : (t2 > TT - 1 ? TT - 1 : t2);
            const float* p = &g_xgT[d][t2][row][bb0];
            nxA = *(const ulonglong2*)(p + 0);
            nxB = *(const ulonglong2*)(p + 4);
            pen0 = (1.0f - __ldg(&masks[(b0)     * TT + t2])) * 1e8f;
            pen1 = (1.0f - __ldg(&masks[(b0 + 1) * TT + t2])) * 1e8f;
        }

        // ---- MAC loop: gate row (regs) x h (broadcast LDS), 8 batches ----
        const float* hc = hbuf[cur];
        #pragma unroll
        for (int k = 0; k < 128; ++k) {
            ulonglong2 hA = *(const ulonglong2*)(hc + k * 8);      // h[k][0..3]
            ulonglong2 hB = *(const ulonglong2*)(hc + k * 8 + 4);  // h[k][4..7]
            ull w2 = pack2(w[k], w[k]);
            fma2(hA.x, w2, a01);
            fma2(hA.y, w2, a23);
            fma2(hB.x, w2, a45);
            fma2(hB.y, w2, a67);
        }

        // ---- gate exchange: [g][kk] -> padded rows of 10 floats ----
        {
            float* gb = gbuf + g * 640 + kk * 10;
            *(ull*)(gb + 0) = a01;
            *(ull*)(gb + 2) = a23;
            *(ull*)(gb + 4) = a45;
            *(ull*)(gb + 6) = a67;
        }
        __syncthreads();

        // ---- c/h update + masked running max (update role) ----
        {
            const float* gb2 = gbuf + uk * 10 + bp * 2;
            float2 gi = *(const float2*)(gb2 + 0 * 640);
            float2 gf = *(const float2*)(gb2 + 1 * 640);
            float2 gg = *(const float2*)(gb2 + 2 * 640);
            float2 go = *(const float2*)(gb2 + 3 * 640);

            c0 = sigf(gf.x) * c0 + sigf(gi.x) * tanhf_(gg.x);
            float hv0 = sigf(go.x) * tanhf_(c0);
            m0 = fmaxf(m0, hv0 - npen0);

            c1 = sigf(gf.y) * c1 + sigf(gi.y) * tanhf_(gg.y);
            float hv1 = sigf(go.y) * tanhf_(c1);
            m1 = fmaxf(m1, hv1 - npen1);

            if (s < TT - 1) {
                // write h into next buffer: local + DSMEM peer
                if (cur) { *(float2*)loc0 = make_float2(hv0, hv1); }
                else     { *(float2*)loc1 = make_float2(hv0, hv1); }
                unsigned ra = cur ? rem0 : rem1;
                asm volatile("st.shared::cluster.v2.f32 [%0], {%1,%2};"
                             :: "r"(ra), "f"(hv0), "f"(hv1) : "memory");
            }
        }

        if (s < TT - 1) {
            // 2-CTA split barrier: orders h pushes + gbuf reuse; syncs CTA
            asm volatile("barrier.cluster.arrive.aligned;" ::: "memory");
            asm volatile("barrier.cluster.wait.aligned;"   ::: "memory");
        }

        cur ^= 1;
        t += tstep;
    }

    // output (update role): (k = K0+uk, batches b0, b0+1)
    out[(b0)     * HID + d * HH + K0 + uk] = m0;
    out[(b0 + 1) * HID + d * HH + K0 + uk] = m1;
}

// ---------------------------------------------------------------------------
extern "C" void kernel_launch(void* const* d_in, const int* in_sizes, int n_in,
                              void* d_out, int out_size)
{
    (void)in_sizes; (void)n_in; (void)out_size;
    const int*   idx   = (const int*)  d_in[0];
    const float* masks = (const float*)d_in[1];
    const float* emb   = (const float*)d_in[2];
    const float* Wih_f = (const float*)d_in[3];
    const float* Whh_f = (const float*)d_in[4];
    const float* bih_f = (const float*)d_in[5];
    const float* bhh_f = (const float*)d_in[6];
    const float* Wih_b = (const float*)d_in[7];
    const float* Whh_b = (const float*)d_in[8];
    const float* bih_b = (const float*)d_in[9];
    const float* bhh_b = (const float*)d_in[10];
    float* out = (float*)d_out;

    embed_gemm<<<dim3(8, TT), 256>>>(idx, emb, Wih_f, bih_f, bhh_f,
                                     Wih_b, bih_b, bhh_b);
    lstm_reg<<<dim3(2, 32, 2), 256>>>(Whh_f, Whh_b, masks, out);
}

// round 8
// speedup vs baseline: 1.0495x; 1.0495x over previous
#include <cuda_runtime.h>

#define BB 256
#define TT 512
#define DD 50
#define HH 128
#define G4 512
#define HID 256

typedef unsigned long long ull;

// ---- device scratch ----
__device__ float g_xgT[2][TT][G4][BB];   // input-gate preactivations [d][t][row][b]

__device__ __forceinline__ float sigf(float x)   { return 1.0f / (1.0f + __expf(-x)); }
__device__ __forceinline__ float tanhf_(float x) { return 2.0f / (1.0f + __expf(-2.0f * x)) - 1.0f; }

__device__ __forceinline__ ull pack2(float a, float b) {
    ull r; asm("mov.b64 %0,{%1,%2};" : "=l"(r) : "f"(a), "f"(b)); return r;
}
__device__ __forceinline__ void unpack2(ull v, float& a, float& b) {
    asm("mov.b64 {%0,%1},%2;" : "=f"(a), "=f"(b) : "l"(v));
}
__device__ __forceinline__ void fma2(ull a, ull b, ull& c) {
    asm("fma.rn.f32x2 %0,%1,%2,%0;" : "+l"(c) : "l"(a), "l"(b));
}
__device__ __forceinline__ unsigned smem_u32(const void* p) {
    unsigned r;
    asm("{ .reg .u64 t; cvta.to.shared.u64 t, %1; cvt.u32.u64 %0, t; }" : "=r"(r) : "l"(p));
    return r;
}

// ---------------------------------------------------------------------------
// Embedding lookup + input-gate GEMM -> transposed xg (unchanged)
// ---------------------------------------------------------------------------
__global__ void __launch_bounds__(256) embed_gemm(
    const int*   __restrict__ idx,
    const float* __restrict__ emb,
    const float* __restrict__ Wih_f, const float* __restrict__ bih_f, const float* __restrict__ bhh_f,
    const float* __restrict__ Wih_b, const float* __restrict__ bih_b, const float* __restrict__ bhh_b)
{
    __shared__ __align__(16) float xsA[16 * DD * 2];
    const int tid = threadIdx.x;
    const int b0  = blockIdx.x * 32;
    const int t   = blockIdx.y;

    for (int i = tid; i < 32 * DD; i += 256) {
        int b = i / DD, k = i - b * DD;
        int id = idx[(b0 + b) * TT + t];
        xsA[(b >> 1) * (2 * DD) + k * 2 + (b & 1)] = emb[id * DD + k];
    }
    __syncthreads();

    #pragma unroll 1
    for (int g = 0; g < 4; ++g) {
        int col = tid + g * 256;
        int dir = col >> 9;
        int n   = col & 511;
        const float* W = dir ? Wih_b : Wih_f;
        float bias = dir ? (bih_b[n] + bhh_b[n]) : (bih_f[n] + bhh_f[n]);

        float w[DD];
        #pragma unroll
        for (int k = 0; k < DD; ++k) w[k] = W[n * DD + k];

        ull acc[16];
        ull bp = pack2(bias, bias);
        #pragma unroll
        for (int p = 0; p < 16; ++p) acc[p] = bp;

        #pragma unroll 2
        for (int k = 0; k < DD; ++k) {
            ull w2 = pack2(w[k], w[k]);
            #pragma unroll
            for (int p = 0; p < 16; ++p) {
                ull x = *(const ull*)&xsA[p * (2 * DD) + k * 2];
                fma2(x, w2, acc[p]);
            }
        }

        float* dst = &g_xgT[dir][t][n][b0];
        #pragma unroll
        for (int p = 0; p < 16; ++p) {
            float a, b; unpack2(acc[p], a, b);
            *(float2*)&dst[2 * p] = make_float2(a, b);
        }
    }
}

// ---------------------------------------------------------------------------
// Persistent LSTM recurrence: weights in registers, K SPLIT across threads.
// grid (2,32,2) cluster(2,1,1); 512 threads/CTA (16 warps -> 4/SMSP).
// Thread (khalf = tid>>8, g = (tid>>6)&3, kk = tid&63): one gate row,
// 64 weight regs (its k-half), 8 batches. Partial gate sums exchanged via
// bank-engineered smem (stride 136), summed by update threads (tid<256).
// ---------------------------------------------------------------------------
// pbuf layout: block = ((khalf*4+g)*4 + pairj), entry = block*136 + kk*2
//   bank(load) = (bp*136*? ) -> stride 136 mod 32 = 8 => banks bp*8+uk*2, all distinct
#define PBS 136
__global__ void __launch_bounds__(512, 1) __cluster_dims__(2, 1, 1)
lstm_ksplit(const float* __restrict__ Whh_f, const float* __restrict__ Whh_b,
            const float* __restrict__ masks, float* __restrict__ out)
{
    __shared__ __align__(16) float hbuf[2][128 * 8];   // h double buffer [k][b]
    __shared__ __align__(16) float pbuf[32 * PBS];     // partial gates

    const int tid   = threadIdx.x;
    const int rank  = blockIdx.x;              // k-half of output == cluster rank
    const int bt    = blockIdx.y;              // 0..31
    const int d     = blockIdx.z;
    const int K0    = rank * 64;
    const int bb0   = bt * 8;

    // MAC role
    const int khalf = tid >> 8;                // input k-half 0/1
    const int g     = (tid >> 6) & 3;          // gate
    const int kk    = tid & 63;                // k-output
    const int row   = g * 128 + K0 + kk;

    // Update role (tid < 256 only)
    const int uk = tid >> 2;                   // 0..63 (for tid<256)
    const int bp = tid & 3;
    const int b0 = bb0 + 2 * bp;

    const float* Whh = d ? Whh_b : Whh_f;

    // ---- weight k-half into registers ----
    float w[64];
    {
        const float4* src = (const float4*)&Whh[row * 128 + khalf * 64];
        #pragma unroll
        for (int q = 0; q < 16; ++q) {
            float4 v = src[q];
            w[4 * q + 0] = v.x; w[4 * q + 1] = v.y;
            w[4 * q + 2] = v.z; w[4 * q + 3] = v.w;
        }
    }
    for (int i = tid; i < 1024; i += 512) hbuf[0][i] = 0.f;

    // peer push addresses (both parities), update role only
    unsigned rem0 = 0, rem1 = 0;
    float *loc0 = 0, *loc1 = 0;
    {
        const unsigned off = (unsigned)(((K0 + uk) * 8 + 2 * bp) * 4);
        unsigned a0 = smem_u32(&hbuf[0][0]) + off;
        unsigned a1 = smem_u32(&hbuf[1][0]) + off;
        unsigned pr = rank ^ 1;
        asm("mapa.shared::cluster.u32 %0, %1, %2;" : "=r"(rem0) : "r"(a0), "r"(pr));
        asm("mapa.shared::cluster.u32 %0, %1, %2;" : "=r"(rem1) : "r"(a1), "r"(pr));
        loc0 = (float*)((char*)&hbuf[0][0] + off);
        loc1 = (float*)((char*)&hbuf[1][0] + off);
    }

    // per-thread state (update role)
    float c0 = 0.f, c1 = 0.f;
    float m0 = -3.0e38f, m1 = -3.0e38f;

    const int tstep = d ? -1 : 1;
    int t = d ? (TT - 1) : 0;

    // xg prefetch: only khalf==0 threads (they seed the accumulators)
    ulonglong2 nxA = {0, 0}, nxB = {0, 0};
    float pen0 = 0.f, pen1 = 0.f;
    if (tid < 256) {
        const float* p = &g_xgT[d][t][row][bb0];
        nxA = *(const ulonglong2*)(p + 0);
        nxB = *(const ulonglong2*)(p + 4);
        pen0 = (1.0f - __ldg(&masks[(b0)     * TT + t])) * 1e8f;
        pen1 = (1.0f - __ldg(&masks[(b0 + 1) * TT + t])) * 1e8f;
    }

    __syncthreads();

    int cur = 0;
    for (int s = 0; s < TT; ++s) {
        ull a01 = nxA.x, a23 = nxA.y, a45 = nxB.x, a67 = nxB.y;
        float npen0 = pen0, npen1 = pen1;

        // prefetch next step (khalf==0 / update threads only)
        if (tid < 256) {
            int t2 = t + tstep;
            t2 = (t2 < 0) ? 0 : (t2 > TT - 1 ? TT - 1 : t2);
            const float* p = &g_xgT[d][t2][row][bb0];
            nxA = *(const ulonglong2*)(p + 0);
            nxB = *(const ulonglong2*)(p + 4);
            pen0 = (1.0f - __ldg(&masks[(b0)     * TT + t2])) * 1e8f;
            pen1 = (1.0f - __ldg(&masks[(b0 + 1) * TT + t2])) * 1e8f;
        }

        // ---- MAC over own k-half: 64 iters x (2 LDS.128 + MOV + 4 FFMA2) ----
        const float* hc = hbuf[cur] + khalf * 64 * 8;
        #pragma unroll
        for (int k = 0; k < 64; ++k) {
            ulonglong2 hA = *(const ulonglong2*)(hc + k * 8);      // h[k][0..3]
            ulonglong2 hB = *(const ulonglong2*)(hc + k * 8 + 4);  // h[k][4..7]
            ull w2 = pack2(w[k], w[k]);
            fma2(hA.x, w2, a01);
            fma2(hA.y, w2, a23);
            fma2(hB.x, w2, a45);
            fma2(hB.y, w2, a67);
        }

        // ---- store partial gates: block=((khalf*4+g)*4+j), contiguous in kk ----
        {
            float* pb = pbuf + (khalf * 4 + g) * 4 * PBS + kk * 2;
            *(ull*)(pb + 0 * PBS) = a01;
            *(ull*)(pb + 1 * PBS) = a23;
            *(ull*)(pb + 2 * PBS) = a45;
            *(ull*)(pb + 3 * PBS) = a67;
        }
        __syncthreads();

        // ---- update role: sum k-halves, c/h update, masked max, push ----
        if (tid < 256) {
            const float* pbb = pbuf + bp * PBS + uk * 2;
            float2 gi0 = *(const float2*)(pbb + (0 * 4 + 0) * 4 * PBS);
            float2 gf0 = *(const float2*)(pbb + (0 * 4 + 1) * 4 * PBS);
            float2 gg0 = *(const float2*)(pbb + (0 * 4 + 2) * 4 * PBS);
            float2 go0 = *(const float2*)(pbb + (0 * 4 + 3) * 4 * PBS);
            float2 gi1 = *(const float2*)(pbb + (1 * 4 + 0) * 4 * PBS);
            float2 gf1 = *(const float2*)(pbb + (1 * 4 + 1) * 4 * PBS);
            float2 gg1 = *(const float2*)(pbb + (1 * 4 + 2) * 4 * PBS);
            float2 go1 = *(const float2*)(pbb + (1 * 4 + 3) * 4 * PBS);

            float gix = gi0.x + gi1.x, gfx = gf0.x + gf1.x;
            float ggx = gg0.x + gg1.x, gox = go0.x + go1.x;
            c0 = sigf(gfx) * c0 + sigf(gix) * tanhf_(ggx);
            float hv0 = sigf(gox) * tanhf_(c0);
            m0 = fmaxf(m0, hv0 - npen0);

            float giy = gi0.y + gi1.y, gfy = gf0.y + gf1.y;
            float ggy = gg0.y + gg1.y, goy = go0.y + go1.y;
            c1 = sigf(gfy) * c1 + sigf(giy) * tanhf_(ggy);
            float hv1 = sigf(goy) * tanhf_(c1);
            m1 = fmaxf(m1, hv1 - npen1);

            if (s < TT - 1) {
                if (cur) { *(float2*)loc0 = make_float2(hv0, hv1); }
                else     { *(float2*)loc1 = make_float2(hv0, hv1); }
                unsigned ra = cur ? rem0 : rem1;
                asm volatile("st.shared::cluster.v2.f32 [%0], {%1,%2};"
                             :: "r"(ra), "f"(hv0), "f"(hv1) : "memory");
            }
        }

        if (s < TT - 1) {
            // cluster barrier: orders h pushes, pbuf reuse; syncs both CTAs
            asm volatile("barrier.cluster.arrive.aligned;" ::: "memory");
            asm volatile("barrier.cluster.wait.aligned;"   ::: "memory");
        }

        cur ^= 1;
        t += tstep;
    }

    if (tid < 256) {
        out[(b0)     * HID + d * HH + K0 + uk] = m0;
        out[(b0 + 1) * HID + d * HH + K0 + uk] = m1;
    }
}

// ---------------------------------------------------------------------------
extern "C" void kernel_launch(void* const* d_in, const int* in_sizes, int n_in,
                              void* d_out, int out_size)
{
    (void)in_sizes; (void)n_in; (void)out_size;
    const int*   idx   = (const int*)  d_in[0];
    const float* masks = (const float*)d_in[1];
    const float* emb   = (const float*)d_in[2];
    const float* Wih_f = (const float*)d_in[3];
    const float* Whh_f = (const float*)d_in[4];
    const float* bih_f = (const float*)d_in[5];
    const float* bhh_f = (const float*)d_in[6];
    const float* Wih_b = (const float*)d_in[7];
    const float* Whh_b = (const float*)d_in[8];
    const float* bih_b = (const float*)d_in[9];
    const float* bhh_b = (const float*)d_in[10];
    float* out = (float*)d_out;

    embed_gemm<<<dim3(8, TT), 256>>>(idx, emb, Wih_f, bih_f, bhh_f,
                                     Wih_b, bih_b, bhh_b);
    lstm_ksplit<<<dim3(2, 32, 2), 512>>>(Whh_f, Whh_b, masks, out);
}